// round 5
// baseline (speedup 1.0000x reference)
#include <cuda_runtime.h>
#include <cstdint>

// WCT: out[b] = alpha*x[b] + (1-alpha)*( M_b * (x[b]-mean_b) + mean_{perm[b]} )
// M_b = cov_{perm[b]}^{1/2} * cov_b^{-1/2}, roots via coupled Newton-Schulz.
// Folded: out = A_b * x + bias_b with A_b = alpha*I + (1-alpha)*M_b.

#define BATCH 16
#define HW 65536
#define NCH 64
#define GBLK 16                 // gram blocks per batch
#define GPIX (HW / GBLK)        // 4096 pixels per gram block
#define ABLK 16                 // apply blocks per batch
#define APIX (HW / ABLK)        // 4096 pixels per apply block
#define NS_ITERS 7
#define MS 68                   // padded row stride (floats) for 64x64 smem matrices
#define XS 68                   // padded row stride (floats) for pixel tiles

// ---- device scratch (static globals; allocation-free) ----
__device__ float g_part[BATCH][GBLK][NCH * NCH];   // per-block gram partials (4 MB)
__device__ float g_psum[BATCH][GBLK][NCH];         // per-block channel-sum partials
__device__ float g_cov [BATCH][NCH * NCH];
__device__ float g_mean[BATCH][NCH];
__device__ float g_half[BATCH][NCH * NCH];         // cov^{1/2}
__device__ float g_invh[BATCH][NCH * NCH];         // cov^{-1/2}
__device__ float g_At  [BATCH][NCH * NCH];         // A^T: g_At[k*64+c] = A[c][k]
__device__ float g_bias[BATCH][NCH];

// ============================================================================
// Kernel 1: Gram + channel sums. grid (GBLK, BATCH), 256 threads.
// 8x8 register blocking; 4 pixel-interleaved groups of 64 threads.
// ============================================================================
__global__ void __launch_bounds__(256) gram_kernel(const float* __restrict__ x) {
    __shared__ float tile[64 * NCH];   // 64 pixels x 64 ch = 16 KB
    __shared__ float red[256];

    const int b   = blockIdx.y;
    const int blk = blockIdx.x;
    const int tid = threadIdx.x;
    const int g   = tid >> 6;          // pixel-interleave group 0..3
    const int u   = tid & 63;
    const int ti  = u >> 3;            // row-tile 0..7  (rows 8*ti..8*ti+7)
    const int tj  = u & 7;             // col-tile 0..7

    float acc[8][8];
#pragma unroll
    for (int i = 0; i < 8; i++)
#pragma unroll
        for (int j = 0; j < 8; j++) acc[i][j] = 0.f;
    float ssum = 0.f;

    const float4* x4 = reinterpret_cast<const float4*>(x) +
                       ((size_t)b * HW + (size_t)blk * GPIX) * (NCH / 4);
    float4* t4 = reinterpret_cast<float4*>(tile);

    for (int t = 0; t < GPIX / 64; ++t) {
        // stage 64 pixels (1024 float4), coalesced
#pragma unroll
        for (int k2 = 0; k2 < 4; ++k2)
            t4[tid + 256 * k2] = x4[(size_t)t * 1024 + tid + 256 * k2];
        __syncthreads();

#pragma unroll 4
        for (int p = g; p < 64; p += 4) {
            const float4 a0 = t4[p * 16 + 2 * ti];
            const float4 a1 = t4[p * 16 + 2 * ti + 1];
            const float4 c0 = t4[p * 16 + 2 * tj];
            const float4 c1 = t4[p * 16 + 2 * tj + 1];
            float av[8] = {a0.x, a0.y, a0.z, a0.w, a1.x, a1.y, a1.z, a1.w};
            float bv[8] = {c0.x, c0.y, c0.z, c0.w, c1.x, c1.y, c1.z, c1.w};
#pragma unroll
            for (int i = 0; i < 8; i++)
#pragma unroll
                for (int j = 0; j < 8; j++) acc[i][j] += av[i] * bv[j];
            ssum += tile[p * NCH + u];
        }
        __syncthreads();
    }

    // deterministic in-block reduction of the 4 pixel-groups
    red[tid] = ssum;
    __syncthreads();
    if (tid < 64)
        g_psum[b][blk][u] = red[u] + red[u + 64] + red[u + 128] + red[u + 192];
    __syncthreads();

#pragma unroll
    for (int e = 0; e < 64; ++e) {
        const int ii = e >> 3, jj = e & 7;
        red[tid] = acc[ii][jj];
        __syncthreads();
        if (tid < 64) {
            float v = red[tid] + red[tid + 64] + red[tid + 128] + red[tid + 192];
            int row = (tid >> 3) * 8 + ii;
            int col = (tid & 7) * 8 + jj;
            g_part[b][blk][row * NCH + col] = v;
        }
        __syncthreads();
    }
}

// ============================================================================
// Kernel 2: reduce partials -> mean, cov. grid BATCH, 256 threads.
// ============================================================================
__global__ void __launch_bounds__(256) cov_kernel() {
    __shared__ float mean_s[NCH];
    const int b = blockIdx.x, tid = threadIdx.x;

    if (tid < NCH) {
        float s = 0.f;
#pragma unroll
        for (int k = 0; k < GBLK; ++k) s += g_psum[b][k][tid];
        float m = s * (1.f / (float)HW);
        mean_s[tid] = m;
        g_mean[b][tid] = m;
    }
    __syncthreads();

    const float inv_d = 1.f / (float)(HW - 1);
    for (int e = tid; e < NCH * NCH; e += 256) {
        float s = 0.f;
#pragma unroll
        for (int k = 0; k < GBLK; ++k) s += g_part[b][k][e];
        int i = e >> 6, j = e & 63;
        g_cov[b][e] = (s - (float)HW * mean_s[i] * mean_s[j]) * inv_d;
    }
}

// ============================================================================
// 64x64 smem matmul helper (stride MS). Thread computes row i, cols j0..j0+15.
// ============================================================================
__device__ __forceinline__ void mm64(const float* __restrict__ A,
                                     const float* __restrict__ B,
                                     float r[16], int i, int j0) {
#pragma unroll
    for (int q = 0; q < 16; q++) r[q] = 0.f;
#pragma unroll 8
    for (int k = 0; k < 64; ++k) {
        float a = A[i * MS + k];
        const float4* b4 = reinterpret_cast<const float4*>(B + k * MS + j0);
        float4 x0 = b4[0], x1 = b4[1], x2 = b4[2], x3 = b4[3];
        r[0]  += a * x0.x; r[1]  += a * x0.y; r[2]  += a * x0.z; r[3]  += a * x0.w;
        r[4]  += a * x1.x; r[5]  += a * x1.y; r[6]  += a * x1.z; r[7]  += a * x1.w;
        r[8]  += a * x2.x; r[9]  += a * x2.y; r[10] += a * x2.z; r[11] += a * x2.w;
        r[12] += a * x3.x; r[13] += a * x3.y; r[14] += a * x3.z; r[15] += a * x3.w;
    }
}

// ============================================================================
// Kernel 3: Newton-Schulz: Y->cov^{1/2}, Z->cov^{-1/2}. grid BATCH, 256 thr.
// Dynamic smem: 3 * 64 * MS floats (52 KB).
// ============================================================================
__global__ void __launch_bounds__(256) ns_kernel() {
    extern __shared__ float dsm[];
    float* sY = dsm;
    float* sZ = sY + 64 * MS;
    float* sT = sZ + 64 * MS;

    const int b = blockIdx.x, tid = threadIdx.x;
    const int i = tid >> 2, j0 = (tid & 3) * 16;

    // infinity-norm of cov (>= largest eigenvalue for SPD)
    if (tid < 64) {
        float s = 0.f;
        for (int j = 0; j < 64; ++j) s += fabsf(g_cov[b][tid * 64 + j]);
        sY[tid] = s;
    }
    __syncthreads();
    if (tid == 0) {
        float m = 0.f;
        for (int r = 0; r < 64; ++r) m = fmaxf(m, sY[r]);
        sT[0] = m;
    }
    __syncthreads();
    const float c = sT[0];
    const float inv_c = 1.f / c;
    __syncthreads();

    for (int e = tid; e < 4096; e += 256) {
        int r = e >> 6, q = e & 63;
        sY[r * MS + q] = g_cov[b][e] * inv_c;
        sZ[r * MS + q] = (r == q) ? 1.f : 0.f;
    }
    __syncthreads();

    float rg[16];
    for (int it = 0; it < NS_ITERS; ++it) {
        // T = 1.5 I - 0.5 * Z*Y
        mm64(sZ, sY, rg, i, j0);
#pragma unroll
        for (int q = 0; q < 16; q++)
            sT[i * MS + j0 + q] = ((i == j0 + q) ? 1.5f : 0.f) - 0.5f * rg[q];
        __syncthreads();
        // Y' = Y*T
        mm64(sY, sT, rg, i, j0);
        __syncthreads();
#pragma unroll
        for (int q = 0; q < 16; q++) sY[i * MS + j0 + q] = rg[q];
        __syncthreads();
        // Z' = T*Z
        mm64(sT, sZ, rg, i, j0);
        __syncthreads();
#pragma unroll
        for (int q = 0; q < 16; q++) sZ[i * MS + j0 + q] = rg[q];
        __syncthreads();
    }

    const float sc = sqrtf(c), isc = rsqrtf(c);
    for (int e = tid; e < 4096; e += 256) {
        int r = e >> 6, q = e & 63;
        g_half[b][e] = sY[r * MS + q] * sc;
        g_invh[b][e] = sZ[r * MS + q] * isc;
    }
}

// ============================================================================
// Kernel 4: A_b = alpha I + (1-alpha) * half[perm[b]] * invh[b] (stored A^T),
//           bias_b = (1-alpha)*(mean[perm[b]] - M*mean[b]). grid BATCH.
// ============================================================================
__global__ void __launch_bounds__(256) comb_kernel(const int* __restrict__ perm,
                                                   const float* __restrict__ alpha) {
    __shared__ float sS[64 * MS], sTi[64 * MS], red[256];
    const int b = blockIdx.x, tid = threadIdx.x;
    const int pb = perm[b];
    const float al = alpha[b];
    const float oma = 1.f - al;

    for (int e = tid; e < 4096; e += 256) {
        int r = e >> 6, q = e & 63;
        sS [r * MS + q] = g_half[pb][e];
        sTi[r * MS + q] = g_invh[b][e];
    }
    __syncthreads();

    const int i = tid >> 2, j0 = (tid & 3) * 16;
    float m[16];
    mm64(sS, sTi, m, i, j0);   // M[i][j0+q]

    float pdot = 0.f;
#pragma unroll
    for (int q = 0; q < 16; q++) {
        int j = j0 + q;
        g_At[b][j * 64 + i] = ((i == j) ? al : 0.f) + oma * m[q];  // A^T[j][i]=A[i][j]
        pdot += m[q] * g_mean[b][j];
    }
    red[tid] = pdot;
    __syncthreads();
    if (tid < 64) {
        int r = tid;
        float dot = red[4 * r] + red[4 * r + 1] + red[4 * r + 2] + red[4 * r + 3];
        g_bias[b][r] = oma * (g_mean[pb][r] - dot);
    }
}

// ============================================================================
// Kernel 5: out[p] = A*x[p] + bias. grid (ABLK, BATCH), 256 threads.
// 256-pixel tiles (padded stride XS), 8px x 8ch register blocking per thread.
// Dynamic smem: 256*XS + 4096 + 64 floats (~86 KB).
// ============================================================================
__global__ void __launch_bounds__(256) apply_kernel(const float* __restrict__ x,
                                                    float* __restrict__ out) {
    extern __shared__ float dsm[];
    float* sx = dsm;                 // 256 * XS
    float* sA = sx + 256 * XS;       // 64*64 (A^T, row k contiguous in c)
    float* sb = sA + 4096;           // 64

    const int b = blockIdx.y, blk = blockIdx.x, tid = threadIdx.x;

    for (int e = tid; e < 4096; e += 256) sA[e] = g_At[b][e];
    if (tid < 64) sb[tid] = g_bias[b][tid];
    __syncthreads();

    const int ci = tid & 7;          // channel group: c0 = 8*ci
    const int pi = tid >> 3;         // pixel slot 0..31 ; pixels pi + 32*s
    const int c0 = ci * 8;

    const float4* x4 = reinterpret_cast<const float4*>(x) +
                       ((size_t)b * HW + (size_t)blk * APIX) * (NCH / 4);
    float4* o4 = reinterpret_cast<float4*>(out) +
                 ((size_t)b * HW + (size_t)blk * APIX) * (NCH / 4);
    float4* sx4 = reinterpret_cast<float4*>(sx);
    const float4* sA4 = reinterpret_cast<const float4*>(sA);

    for (int t = 0; t < APIX / 256; ++t) {
        // stage 256 pixels into padded rows
#pragma unroll
        for (int k2 = 0; k2 < 16; ++k2) {
            int f = tid + 256 * k2;
            int p = f >> 4, q = f & 15;
            sx4[p * (XS / 4) + q] = x4[(size_t)t * 4096 + f];
        }
        __syncthreads();

        float acc[8][8];
#pragma unroll
        for (int s = 0; s < 8; s++)
#pragma unroll
            for (int cc = 0; cc < 8; cc++) acc[s][cc] = sb[c0 + cc];

#pragma unroll 8
        for (int k = 0; k < 64; ++k) {
            const float4 a0 = sA4[k * 16 + 2 * ci];
            const float4 a1 = sA4[k * 16 + 2 * ci + 1];
            float av[8] = {a0.x, a0.y, a0.z, a0.w, a1.x, a1.y, a1.z, a1.w};
#pragma unroll
            for (int s = 0; s < 8; s++) {
                float xv = sx[(pi + 32 * s) * XS + k];
#pragma unroll
                for (int cc = 0; cc < 8; cc++) acc[s][cc] += xv * av[cc];
            }
        }
        __syncthreads();

#pragma unroll
        for (int s = 0; s < 8; s++) {
            int p = pi + 32 * s;
            o4[(size_t)t * 4096 + p * 16 + 2 * ci] =
                make_float4(acc[s][0], acc[s][1], acc[s][2], acc[s][3]);
            o4[(size_t)t * 4096 + p * 16 + 2 * ci + 1] =
                make_float4(acc[s][4], acc[s][5], acc[s][6], acc[s][7]);
        }
    }
}

// ============================================================================
extern "C" void kernel_launch(void* const* d_in, const int* in_sizes, int n_in,
                              void* d_out, int out_size) {
    (void)in_sizes; (void)n_in; (void)out_size;
    const float* x     = (const float*)d_in[0];
    const int*   perm  = (const int*)d_in[1];
    const float* alpha = (const float*)d_in[2];
    float*       out   = (float*)d_out;

    const int ns_smem    = 3 * 64 * MS * (int)sizeof(float);              // 52224 B
    const int apply_smem = (256 * XS + 4096 + 64) * (int)sizeof(float);   // 86272 B
    cudaFuncSetAttribute(ns_kernel, cudaFuncAttributeMaxDynamicSharedMemorySize, ns_smem);
    cudaFuncSetAttribute(apply_kernel, cudaFuncAttributeMaxDynamicSharedMemorySize, apply_smem);

    gram_kernel<<<dim3(GBLK, BATCH), 256>>>(x);
    cov_kernel<<<BATCH, 256>>>();
    ns_kernel<<<BATCH, 256, ns_smem>>>();
    comb_kernel<<<BATCH, 256>>>(perm, alpha);
    apply_kernel<<<dim3(ABLK, BATCH), 256, apply_smem>>>(x, out);
}

// round 6
// speedup vs baseline: 1.0080x; 1.0080x over previous
#include <cuda_runtime.h>
#include <cstdint>

// WCT: out[b] = alpha*x[b] + (1-alpha)*( M_b * (x[b]-mean_b) + mean_{perm[b]} )
// M_b = cov_{perm[b]}^{1/2} * cov_b^{-1/2}, roots via coupled Newton-Schulz.
// Folded: out = A_b * x + bias_b with A_b = alpha*I + (1-alpha)*M_b.

#define BATCH 16
#define HW 65536
#define NCH 64
#define GBLK 16                 // gram blocks per batch
#define GPIX (HW / GBLK)        // 4096 pixels per gram block
#define ABLK 16                 // apply blocks per batch
#define APIX (HW / ABLK)        // 4096 pixels per apply block
#define NS_ITERS 7
#define MS 68                   // padded row stride (floats) for 64x64 smem matrices
#define XS 68                   // padded row stride (floats) for pixel tiles

// ---- device scratch (static globals; allocation-free) ----
__device__ float g_part[BATCH][GBLK][NCH * NCH];   // per-block gram partials (4 MB)
__device__ float g_psum[BATCH][GBLK][NCH];         // per-block channel-sum partials
__device__ float g_cov [BATCH][NCH * NCH];
__device__ float g_mean[BATCH][NCH];
__device__ float g_half[BATCH][NCH * NCH];         // cov^{1/2}
__device__ float g_invh[BATCH][NCH * NCH];         // cov^{-1/2}
__device__ float g_At  [BATCH][NCH * NCH];         // A^T: g_At[k*64+c] = A[c][k]
__device__ float g_bias[BATCH][NCH];

// ============================================================================
// Kernel 1: Gram + channel sums. grid (GBLK, BATCH), 256 threads.
// 8x8 register blocking; 4 pixel-interleaved groups of 64 threads.
// ============================================================================
__global__ void __launch_bounds__(256) gram_kernel(const float* __restrict__ x) {
    __shared__ float tile[64 * NCH];   // 64 pixels x 64 ch = 16 KB
    __shared__ float red[256];

    const int b   = blockIdx.y;
    const int blk = blockIdx.x;
    const int tid = threadIdx.x;
    const int g   = tid >> 6;          // pixel-interleave group 0..3
    const int u   = tid & 63;
    const int ti  = u >> 3;            // row-tile 0..7  (rows 8*ti..8*ti+7)
    const int tj  = u & 7;             // col-tile 0..7

    float acc[8][8];
#pragma unroll
    for (int i = 0; i < 8; i++)
#pragma unroll
        for (int j = 0; j < 8; j++) acc[i][j] = 0.f;
    float ssum = 0.f;

    const float4* x4 = reinterpret_cast<const float4*>(x) +
                       ((size_t)b * HW + (size_t)blk * GPIX) * (NCH / 4);
    float4* t4 = reinterpret_cast<float4*>(tile);

    for (int t = 0; t < GPIX / 64; ++t) {
        // stage 64 pixels (1024 float4), coalesced
#pragma unroll
        for (int k2 = 0; k2 < 4; ++k2)
            t4[tid + 256 * k2] = x4[(size_t)t * 1024 + tid + 256 * k2];
        __syncthreads();

#pragma unroll 4
        for (int p = g; p < 64; p += 4) {
            const float4 a0 = t4[p * 16 + 2 * ti];
            const float4 a1 = t4[p * 16 + 2 * ti + 1];
            const float4 c0 = t4[p * 16 + 2 * tj];
            const float4 c1 = t4[p * 16 + 2 * tj + 1];
            float av[8] = {a0.x, a0.y, a0.z, a0.w, a1.x, a1.y, a1.z, a1.w};
            float bv[8] = {c0.x, c0.y, c0.z, c0.w, c1.x, c1.y, c1.z, c1.w};
#pragma unroll
            for (int i = 0; i < 8; i++)
#pragma unroll
                for (int j = 0; j < 8; j++) acc[i][j] += av[i] * bv[j];
            ssum += tile[p * NCH + u];
        }
        __syncthreads();
    }

    // deterministic in-block reduction of the 4 pixel-groups
    red[tid] = ssum;
    __syncthreads();
    if (tid < 64)
        g_psum[b][blk][u] = red[u] + red[u + 64] + red[u + 128] + red[u + 192];
    __syncthreads();

#pragma unroll
    for (int e = 0; e < 64; ++e) {
        const int ii = e >> 3, jj = e & 7;
        red[tid] = acc[ii][jj];
        __syncthreads();
        if (tid < 64) {
            float v = red[tid] + red[tid + 64] + red[tid + 128] + red[tid + 192];
            int row = (tid >> 3) * 8 + ii;
            int col = (tid & 7) * 8 + jj;
            g_part[b][blk][row * NCH + col] = v;
        }
        __syncthreads();
    }
}

// ============================================================================
// Kernel 2: reduce partials -> mean, cov. grid BATCH, 256 threads.
// ============================================================================
__global__ void __launch_bounds__(256) cov_kernel() {
    __shared__ float mean_s[NCH];
    const int b = blockIdx.x, tid = threadIdx.x;

    if (tid < NCH) {
        float s = 0.f;
#pragma unroll
        for (int k = 0; k < GBLK; ++k) s += g_psum[b][k][tid];
        float m = s * (1.f / (float)HW);
        mean_s[tid] = m;
        g_mean[b][tid] = m;
    }
    __syncthreads();

    const float inv_d = 1.f / (float)(HW - 1);
    for (int e = tid; e < NCH * NCH; e += 256) {
        float s = 0.f;
#pragma unroll
        for (int k = 0; k < GBLK; ++k) s += g_part[b][k][e];
        int i = e >> 6, j = e & 63;
        g_cov[b][e] = (s - (float)HW * mean_s[i] * mean_s[j]) * inv_d;
    }
}

// ============================================================================
// 64x64 smem matmul helper (stride MS). Thread computes row i, cols j0..j0+15.
// ============================================================================
__device__ __forceinline__ void mm64(const float* __restrict__ A,
                                     const float* __restrict__ B,
                                     float r[16], int i, int j0) {
#pragma unroll
    for (int q = 0; q < 16; q++) r[q] = 0.f;
#pragma unroll 8
    for (int k = 0; k < 64; ++k) {
        float a = A[i * MS + k];
        const float4* b4 = reinterpret_cast<const float4*>(B + k * MS + j0);
        float4 x0 = b4[0], x1 = b4[1], x2 = b4[2], x3 = b4[3];
        r[0]  += a * x0.x; r[1]  += a * x0.y; r[2]  += a * x0.z; r[3]  += a * x0.w;
        r[4]  += a * x1.x; r[5]  += a * x1.y; r[6]  += a * x1.z; r[7]  += a * x1.w;
        r[8]  += a * x2.x; r[9]  += a * x2.y; r[10] += a * x2.z; r[11] += a * x2.w;
        r[12] += a * x3.x; r[13] += a * x3.y; r[14] += a * x3.z; r[15] += a * x3.w;
    }
}

// ============================================================================
// Kernel 3: Newton-Schulz: Y->cov^{1/2}, Z->cov^{-1/2}. grid BATCH, 256 thr.
// Dynamic smem: 3 * 64 * MS floats (52 KB).
// ============================================================================
__global__ void __launch_bounds__(256) ns_kernel() {
    extern __shared__ float dsm[];
    float* sY = dsm;
    float* sZ = sY + 64 * MS;
    float* sT = sZ + 64 * MS;

    const int b = blockIdx.x, tid = threadIdx.x;
    const int i = tid >> 2, j0 = (tid & 3) * 16;

    // infinity-norm of cov (>= largest eigenvalue for SPD)
    if (tid < 64) {
        float s = 0.f;
        for (int j = 0; j < 64; ++j) s += fabsf(g_cov[b][tid * 64 + j]);
        sY[tid] = s;
    }
    __syncthreads();
    if (tid == 0) {
        float m = 0.f;
        for (int r = 0; r < 64; ++r) m = fmaxf(m, sY[r]);
        sT[0] = m;
    }
    __syncthreads();
    const float c = sT[0];
    const float inv_c = 1.f / c;
    __syncthreads();

    for (int e = tid; e < 4096; e += 256) {
        int r = e >> 6, q = e & 63;
        sY[r * MS + q] = g_cov[b][e] * inv_c;
        sZ[r * MS + q] = (r == q) ? 1.f : 0.f;
    }
    __syncthreads();

    float rg[16];
    for (int it = 0; it < NS_ITERS; ++it) {
        // T = 1.5 I - 0.5 * Z*Y
        mm64(sZ, sY, rg, i, j0);
#pragma unroll
        for (int q = 0; q < 16; q++)
            sT[i * MS + j0 + q] = ((i == j0 + q) ? 1.5f : 0.f) - 0.5f * rg[q];
        __syncthreads();
        // Y' = Y*T
        mm64(sY, sT, rg, i, j0);
        __syncthreads();
#pragma unroll
        for (int q = 0; q < 16; q++) sY[i * MS + j0 + q] = rg[q];
        __syncthreads();
        // Z' = T*Z
        mm64(sT, sZ, rg, i, j0);
        __syncthreads();
#pragma unroll
        for (int q = 0; q < 16; q++) sZ[i * MS + j0 + q] = rg[q];
        __syncthreads();
    }

    const float sc = sqrtf(c), isc = rsqrtf(c);
    for (int e = tid; e < 4096; e += 256) {
        int r = e >> 6, q = e & 63;
        g_half[b][e] = sY[r * MS + q] * sc;
        g_invh[b][e] = sZ[r * MS + q] * isc;
    }
}

// ============================================================================
// Kernel 4: A_b = alpha I + (1-alpha) * half[perm[b]] * invh[b] (stored A^T),
//           bias_b = (1-alpha)*(mean[perm[b]] - M*mean[b]). grid BATCH.
// ============================================================================
__global__ void __launch_bounds__(256) comb_kernel(const int* __restrict__ perm,
                                                   const float* __restrict__ alpha) {
    __shared__ float sS[64 * MS], sTi[64 * MS], red[256];
    const int b = blockIdx.x, tid = threadIdx.x;
    const int pb = perm[b];
    const float al = alpha[b];
    const float oma = 1.f - al;

    for (int e = tid; e < 4096; e += 256) {
        int r = e >> 6, q = e & 63;
        sS [r * MS + q] = g_half[pb][e];
        sTi[r * MS + q] = g_invh[b][e];
    }
    __syncthreads();

    const int i = tid >> 2, j0 = (tid & 3) * 16;
    float m[16];
    mm64(sS, sTi, m, i, j0);   // M[i][j0+q]

    float pdot = 0.f;
#pragma unroll
    for (int q = 0; q < 16; q++) {
        int j = j0 + q;
        g_At[b][j * 64 + i] = ((i == j) ? al : 0.f) + oma * m[q];  // A^T[j][i]=A[i][j]
        pdot += m[q] * g_mean[b][j];
    }
    red[tid] = pdot;
    __syncthreads();
    if (tid < 64) {
        int r = tid;
        float dot = red[4 * r] + red[4 * r + 1] + red[4 * r + 2] + red[4 * r + 3];
        g_bias[b][r] = oma * (g_mean[pb][r] - dot);
    }
}

// ============================================================================
// Kernel 5: out[p] = A*x[p] + bias. grid (ABLK, BATCH), 256 threads.
// 256-pixel tiles (padded stride XS), 8px x 8ch register blocking per thread.
// Dynamic smem: 256*XS + 4096 + 64 floats (~86 KB).
// ============================================================================
__global__ void __launch_bounds__(256) apply_kernel(const float* __restrict__ x,
                                                    float* __restrict__ out) {
    extern __shared__ float dsm[];
    float* sx = dsm;                 // 256 * XS
    float* sA = sx + 256 * XS;       // 64*64 (A^T, row k contiguous in c)
    float* sb = sA + 4096;           // 64

    const int b = blockIdx.y, blk = blockIdx.x, tid = threadIdx.x;

    for (int e = tid; e < 4096; e += 256) sA[e] = g_At[b][e];
    if (tid < 64) sb[tid] = g_bias[b][tid];
    __syncthreads();

    const int ci = tid & 7;          // channel group: c0 = 8*ci
    const int pi = tid >> 3;         // pixel slot 0..31 ; pixels pi + 32*s
    const int c0 = ci * 8;

    const float4* x4 = reinterpret_cast<const float4*>(x) +
                       ((size_t)b * HW + (size_t)blk * APIX) * (NCH / 4);
    float4* o4 = reinterpret_cast<float4*>(out) +
                 ((size_t)b * HW + (size_t)blk * APIX) * (NCH / 4);
    float4* sx4 = reinterpret_cast<float4*>(sx);
    const float4* sA4 = reinterpret_cast<const float4*>(sA);

    for (int t = 0; t < APIX / 256; ++t) {
        // stage 256 pixels into padded rows
#pragma unroll
        for (int k2 = 0; k2 < 16; ++k2) {
            int f = tid + 256 * k2;
            int p = f >> 4, q = f & 15;
            sx4[p * (XS / 4) + q] = x4[(size_t)t * 4096 + f];
        }
        __syncthreads();

        float acc[8][8];
#pragma unroll
        for (int s = 0; s < 8; s++)
#pragma unroll
            for (int cc = 0; cc < 8; cc++) acc[s][cc] = sb[c0 + cc];

#pragma unroll 8
        for (int k = 0; k < 64; ++k) {
            const float4 a0 = sA4[k * 16 + 2 * ci];
            const float4 a1 = sA4[k * 16 + 2 * ci + 1];
            float av[8] = {a0.x, a0.y, a0.z, a0.w, a1.x, a1.y, a1.z, a1.w};
#pragma unroll
            for (int s = 0; s < 8; s++) {
                float xv = sx[(pi + 32 * s) * XS + k];
#pragma unroll
                for (int cc = 0; cc < 8; cc++) acc[s][cc] += xv * av[cc];
            }
        }
        __syncthreads();

#pragma unroll
        for (int s = 0; s < 8; s++) {
            int p = pi + 32 * s;
            o4[(size_t)t * 4096 + p * 16 + 2 * ci] =
                make_float4(acc[s][0], acc[s][1], acc[s][2], acc[s][3]);
            o4[(size_t)t * 4096 + p * 16 + 2 * ci + 1] =
                make_float4(acc[s][4], acc[s][5], acc[s][6], acc[s][7]);
        }
    }
}

// ============================================================================
extern "C" void kernel_launch(void* const* d_in, const int* in_sizes, int n_in,
                              void* d_out, int out_size) {
    (void)in_sizes; (void)n_in; (void)out_size;
    const float* x     = (const float*)d_in[0];
    const int*   perm  = (const int*)d_in[1];
    const float* alpha = (const float*)d_in[2];
    float*       out   = (float*)d_out;

    const int ns_smem    = 3 * 64 * MS * (int)sizeof(float);              // 52224 B
    const int apply_smem = (256 * XS + 4096 + 64) * (int)sizeof(float);   // 86272 B
    cudaFuncSetAttribute(ns_kernel, cudaFuncAttributeMaxDynamicSharedMemorySize, ns_smem);
    cudaFuncSetAttribute(apply_kernel, cudaFuncAttributeMaxDynamicSharedMemorySize, apply_smem);

    gram_kernel<<<dim3(GBLK, BATCH), 256>>>(x);
    cov_kernel<<<BATCH, 256>>>();
    ns_kernel<<<BATCH, 256, ns_smem>>>();
    comb_kernel<<<BATCH, 256>>>(perm, alpha);
    apply_kernel<<<dim3(ABLK, BATCH), 256, apply_smem>>>(x, out);
}

// round 7
// speedup vs baseline: 1.0434x; 1.0352x over previous
#include <cuda_runtime.h>
#include <cstdint>

// WCT: out[b] = alpha*x[b] + (1-alpha)*( M_b * (x[b]-mean_b) + mean_{perm[b]} )
// M_b = cov_{perm[b]}^{1/2} * cov_b^{-1/2}, roots via coupled Newton-Schulz.
// Folded: out = A_b * x + bias_b with A_b = alpha*I + (1-alpha)*M_b.
// This revision: packed fma.rn.f32x2 everywhere (2x fp32 issue rate),
// 512-thread NS with concurrent Y*T / T*Z halves, 512-thread comb.

#define BATCH 16
#define HW 65536
#define NCH 64
#define GBLK 16                 // gram blocks per batch
#define GPIX (HW / GBLK)        // 4096 pixels per gram block
#define ABLK 16                 // apply blocks per batch
#define APIX (HW / ABLK)        // 4096 pixels per apply block
#define NS_ITERS 6
#define MS 68                   // padded row stride (floats) for 64x64 smem matrices
#define XS 68                   // padded row stride (floats) for pixel tiles

// ---- device scratch (static globals; allocation-free) ----
__device__ float g_part[BATCH][GBLK][NCH * NCH];   // per-block gram partials
__device__ float g_psum[BATCH][GBLK][NCH];         // per-block channel-sum partials
__device__ float g_cov [BATCH][NCH * NCH];
__device__ float g_mean[BATCH][NCH];
__device__ float g_half[BATCH][NCH * NCH];         // cov^{1/2}
__device__ float g_invh[BATCH][NCH * NCH];         // cov^{-1/2}
__device__ float g_At  [BATCH][NCH * NCH];         // A^T: g_At[k*64+c] = A[c][k]
__device__ float g_bias[BATCH][NCH];

// ---- packed f32x2 helpers ----
__device__ __forceinline__ void ffma2(unsigned long long& d,
                                      unsigned long long a,
                                      unsigned long long b) {
    asm("fma.rn.f32x2 %0, %1, %2, %0;" : "+l"(d) : "l"(a), "l"(b));
}
__device__ __forceinline__ unsigned long long dup2f(float v) {
    unsigned long long r;
    unsigned u = __float_as_uint(v);
    asm("mov.b64 %0, {%1, %1};" : "=l"(r) : "r"(u));
    return r;
}
__device__ __forceinline__ float lo32(unsigned long long v) {
    return __uint_as_float((unsigned)v);
}
__device__ __forceinline__ float hi32(unsigned long long v) {
    return __uint_as_float((unsigned)(v >> 32));
}

// ============================================================================
// Kernel 1: Gram + channel sums. grid (GBLK, BATCH), 256 threads.
// 8x8 register blocking (f32x2: 8x4 packed pairs); 4 pixel-interleaved groups.
// ============================================================================
__global__ void __launch_bounds__(256) gram_kernel(const float* __restrict__ x) {
    __shared__ float tile[64 * NCH];   // 64 pixels x 64 ch = 16 KB
    __shared__ float red[256];

    const int b   = blockIdx.y;
    const int blk = blockIdx.x;
    const int tid = threadIdx.x;
    const int g   = tid >> 6;          // pixel-interleave group 0..3
    const int u   = tid & 63;
    const int ti  = u >> 3;            // row-tile 0..7  (rows 8*ti..8*ti+7)
    const int tj  = u & 7;             // col-tile 0..7

    unsigned long long acc2[8][4];
#pragma unroll
    for (int i = 0; i < 8; i++)
#pragma unroll
        for (int j = 0; j < 4; j++) acc2[i][j] = 0ull;
    float ssum = 0.f;

    const float4* x4 = reinterpret_cast<const float4*>(x) +
                       ((size_t)b * HW + (size_t)blk * GPIX) * (NCH / 4);
    float4* t4 = reinterpret_cast<float4*>(tile);
    const ulonglong2* tb2 = reinterpret_cast<const ulonglong2*>(tile);

    for (int t = 0; t < GPIX / 64; ++t) {
        // stage 64 pixels (1024 float4), coalesced
#pragma unroll
        for (int k2 = 0; k2 < 4; ++k2)
            t4[tid + 256 * k2] = x4[(size_t)t * 1024 + tid + 256 * k2];
        __syncthreads();

#pragma unroll 4
        for (int p = g; p < 64; p += 4) {
            const float4 a0 = t4[p * 16 + 2 * ti];
            const float4 a1 = t4[p * 16 + 2 * ti + 1];
            const ulonglong2 b0 = tb2[p * 16 + 2 * tj];
            const ulonglong2 b1 = tb2[p * 16 + 2 * tj + 1];
            float av[8] = {a0.x, a0.y, a0.z, a0.w, a1.x, a1.y, a1.z, a1.w};
            unsigned long long bp[4] = {b0.x, b0.y, b1.x, b1.y};
#pragma unroll
            for (int i = 0; i < 8; i++) {
                unsigned long long ad = dup2f(av[i]);
#pragma unroll
                for (int j = 0; j < 4; j++) ffma2(acc2[i][j], ad, bp[j]);
            }
            ssum += tile[p * NCH + u];
        }
        __syncthreads();
    }

    // deterministic in-block reduction of the 4 pixel-groups
    red[tid] = ssum;
    __syncthreads();
    if (tid < 64)
        g_psum[b][blk][u] = red[u] + red[u + 64] + red[u + 128] + red[u + 192];
    __syncthreads();

#pragma unroll
    for (int e = 0; e < 64; ++e) {
        const int ii = e >> 3, jj = e & 7;
        const unsigned long long v2 = acc2[ii][jj >> 1];
        red[tid] = (jj & 1) ? hi32(v2) : lo32(v2);
        __syncthreads();
        if (tid < 64) {
            float v = red[tid] + red[tid + 64] + red[tid + 128] + red[tid + 192];
            int row = (tid >> 3) * 8 + ii;
            int col = (tid & 7) * 8 + jj;
            g_part[b][blk][row * NCH + col] = v;
        }
        __syncthreads();
    }
}

// ============================================================================
// Kernel 2: reduce partials -> mean, cov. grid BATCH, 256 threads.
// ============================================================================
__global__ void __launch_bounds__(256) cov_kernel() {
    __shared__ float mean_s[NCH];
    const int b = blockIdx.x, tid = threadIdx.x;

    if (tid < NCH) {
        float s = 0.f;
#pragma unroll
        for (int k = 0; k < GBLK; ++k) s += g_psum[b][k][tid];
        float m = s * (1.f / (float)HW);
        mean_s[tid] = m;
        g_mean[b][tid] = m;
    }
    __syncthreads();

    const float inv_d = 1.f / (float)(HW - 1);
    for (int e = tid; e < NCH * NCH; e += 256) {
        float s = 0.f;
#pragma unroll
        for (int k = 0; k < GBLK; ++k) s += g_part[b][k][e];
        int i = e >> 6, j = e & 63;
        g_cov[b][e] = (s - (float)HW * mean_s[i] * mean_s[j]) * inv_d;
    }
}

// ============================================================================
// 64x64 smem matmul helpers (stride MS), packed f32x2.
// mm64p : thread computes row i, cols j0..j0+15 (8 packed pairs).
// mm64p8: thread computes row i, cols j0..j0+7  (4 packed pairs).
// ============================================================================
__device__ __forceinline__ void mm64p(const float* __restrict__ A,
                                      const float* __restrict__ B,
                                      unsigned long long r2[8], int i, int j0) {
#pragma unroll
    for (int q = 0; q < 8; q++) r2[q] = 0ull;
#pragma unroll 8
    for (int k = 0; k < 64; ++k) {
        unsigned long long ad = dup2f(A[i * MS + k]);
        const ulonglong2* b2 = reinterpret_cast<const ulonglong2*>(B + k * MS + j0);
        ulonglong2 x0 = b2[0], x1 = b2[1], x2 = b2[2], x3 = b2[3];
        ffma2(r2[0], ad, x0.x); ffma2(r2[1], ad, x0.y);
        ffma2(r2[2], ad, x1.x); ffma2(r2[3], ad, x1.y);
        ffma2(r2[4], ad, x2.x); ffma2(r2[5], ad, x2.y);
        ffma2(r2[6], ad, x3.x); ffma2(r2[7], ad, x3.y);
    }
}

__device__ __forceinline__ void mm64p8(const float* __restrict__ A,
                                       const float* __restrict__ B,
                                       unsigned long long r2[4], int i, int j0) {
#pragma unroll
    for (int q = 0; q < 4; q++) r2[q] = 0ull;
#pragma unroll 8
    for (int k = 0; k < 64; ++k) {
        unsigned long long ad = dup2f(A[i * MS + k]);
        const ulonglong2* b2 = reinterpret_cast<const ulonglong2*>(B + k * MS + j0);
        ulonglong2 x0 = b2[0], x1 = b2[1];
        ffma2(r2[0], ad, x0.x); ffma2(r2[1], ad, x0.y);
        ffma2(r2[2], ad, x1.x); ffma2(r2[3], ad, x1.y);
    }
}

// ============================================================================
// Kernel 3: Newton-Schulz: Y->cov^{1/2}, Z->cov^{-1/2}. grid BATCH, 512 thr.
// T-phase on all 512 threads (8-wide); Y*T and T*Z concurrently on halves.
// Dynamic smem: 3 * 64 * MS floats (52 KB).
// ============================================================================
__global__ void __launch_bounds__(512) ns_kernel() {
    extern __shared__ float dsm[];
    float* sY = dsm;
    float* sZ = sY + 64 * MS;
    float* sT = sZ + 64 * MS;

    const int b = blockIdx.x, tid = threadIdx.x;
    const int i8  = tid >> 3, j8 = (tid & 7) * 8;            // T-phase mapping
    const int u   = tid & 255;
    const int i16 = u >> 2, j16 = (u & 3) * 16;              // half-phase mapping

    // infinity-norm of cov (>= largest eigenvalue for SPD)
    if (tid < 64) {
        float s = 0.f;
        for (int j = 0; j < 64; ++j) s += fabsf(g_cov[b][tid * 64 + j]);
        sY[tid] = s;
    }
    __syncthreads();
    if (tid == 0) {
        float m = 0.f;
        for (int r = 0; r < 64; ++r) m = fmaxf(m, sY[r]);
        sT[0] = m;
    }
    __syncthreads();
    const float c = sT[0];
    const float inv_c = 1.f / c;
    __syncthreads();

    for (int e = tid; e < 4096; e += 512) {
        int r = e >> 6, q = e & 63;
        sY[r * MS + q] = g_cov[b][e] * inv_c;
        sZ[r * MS + q] = (r == q) ? 1.f : 0.f;
    }
    __syncthreads();

    for (int it = 0; it < NS_ITERS; ++it) {
        // T = 1.5 I - 0.5 * Z*Y   (all 512 threads, 8-wide)
        unsigned long long t2[4];
        mm64p8(sZ, sY, t2, i8, j8);
#pragma unroll
        for (int q = 0; q < 4; q++) {
            int j = j8 + 2 * q;
            sT[i8 * MS + j]     = ((i8 == j)     ? 1.5f : 0.f) - 0.5f * lo32(t2[q]);
            sT[i8 * MS + j + 1] = ((i8 == j + 1) ? 1.5f : 0.f) - 0.5f * hi32(t2[q]);
        }
        __syncthreads();

        // Y' = Y*T (threads 0..255), Z' = T*Z (threads 256..511), concurrent
        unsigned long long r2[8];
        if (tid < 256) mm64p(sY, sT, r2, i16, j16);
        else           mm64p(sT, sZ, r2, i16, j16);
        __syncthreads();
        float* dst = (tid < 256) ? sY : sZ;
#pragma unroll
        for (int q = 0; q < 8; q++) {
            dst[i16 * MS + j16 + 2 * q]     = lo32(r2[q]);
            dst[i16 * MS + j16 + 2 * q + 1] = hi32(r2[q]);
        }
        __syncthreads();
    }

    const float sc = sqrtf(c), isc = rsqrtf(c);
    for (int e = tid; e < 4096; e += 512) {
        int r = e >> 6, q = e & 63;
        g_half[b][e] = sY[r * MS + q] * sc;
        g_invh[b][e] = sZ[r * MS + q] * isc;
    }
}

// ============================================================================
// Kernel 4: A_b = alpha I + (1-alpha) * half[perm[b]] * invh[b] (stored A^T),
//           bias_b = (1-alpha)*(mean[perm[b]] - M*mean[b]). grid BATCH, 512.
// ============================================================================
__global__ void __launch_bounds__(512) comb_kernel(const int* __restrict__ perm,
                                                   const float* __restrict__ alpha) {
    __shared__ float sS[64 * MS], sTi[64 * MS], red[512];
    const int b = blockIdx.x, tid = threadIdx.x;
    const int pb = perm[b];
    const float al = alpha[b];
    const float oma = 1.f - al;

    for (int e = tid; e < 4096; e += 512) {
        int r = e >> 6, q = e & 63;
        sS [r * MS + q] = g_half[pb][e];
        sTi[r * MS + q] = g_invh[b][e];
    }
    __syncthreads();

    const int i = tid >> 3, j0 = (tid & 7) * 8;
    unsigned long long m2[4];
    mm64p8(sS, sTi, m2, i, j0);   // M[i][j0..j0+7]

    float m[8];
#pragma unroll
    for (int q = 0; q < 4; q++) { m[2 * q] = lo32(m2[q]); m[2 * q + 1] = hi32(m2[q]); }

    float pdot = 0.f;
#pragma unroll
    for (int q = 0; q < 8; q++) {
        int j = j0 + q;
        g_At[b][j * 64 + i] = ((i == j) ? al : 0.f) + oma * m[q];  // A^T[j][i]=A[i][j]
        pdot += m[q] * g_mean[b][j];
    }
    red[tid] = pdot;
    __syncthreads();
    if (tid < 64) {
        float dot = 0.f;
#pragma unroll
        for (int t = 0; t < 8; t++) dot += red[tid * 8 + t];
        g_bias[b][tid] = oma * (g_mean[pb][tid] - dot);
    }
}

// ============================================================================
// Kernel 5: out[p] = A*x[p] + bias. grid (ABLK, BATCH), 256 threads.
// 256-pixel tiles (padded stride XS), 8px x 8ch (4 packed pairs) per thread.
// Dynamic smem: 256*XS + 4096 + 64 floats (~86 KB).
// ============================================================================
__global__ void __launch_bounds__(256) apply_kernel(const float* __restrict__ x,
                                                    float* __restrict__ out) {
    extern __shared__ float dsm[];
    float* sx = dsm;                 // 256 * XS
    float* sA = sx + 256 * XS;       // 64*64 (A^T, row k contiguous in c)
    float* sb = sA + 4096;           // 64

    const int b = blockIdx.y, blk = blockIdx.x, tid = threadIdx.x;

    for (int e = tid; e < 4096; e += 256) sA[e] = g_At[b][e];
    if (tid < 64) sb[tid] = g_bias[b][tid];
    __syncthreads();

    const int ci = tid & 7;          // channel group: c0 = 8*ci
    const int pi = tid >> 3;         // pixel slot 0..31 ; pixels pi + 32*s
    const int c0 = ci * 8;

    const float4* x4 = reinterpret_cast<const float4*>(x) +
                       ((size_t)b * HW + (size_t)blk * APIX) * (NCH / 4);
    float4* o4 = reinterpret_cast<float4*>(out) +
                 ((size_t)b * HW + (size_t)blk * APIX) * (NCH / 4);
    float4* sx4 = reinterpret_cast<float4*>(sx);
    const ulonglong2* sA2 = reinterpret_cast<const ulonglong2*>(sA);
    const unsigned long long* sb2 =
        reinterpret_cast<const unsigned long long*>(sb + c0);

    for (int t = 0; t < APIX / 256; ++t) {
        // stage 256 pixels into padded rows
#pragma unroll
        for (int k2 = 0; k2 < 16; ++k2) {
            int f = tid + 256 * k2;
            int p = f >> 4, q = f & 15;
            sx4[p * (XS / 4) + q] = x4[(size_t)t * 4096 + f];
        }
        __syncthreads();

        unsigned long long acc2[8][4];
#pragma unroll
        for (int s = 0; s < 8; s++)
#pragma unroll
            for (int j = 0; j < 4; j++) acc2[s][j] = sb2[j];

#pragma unroll 8
        for (int k = 0; k < 64; ++k) {
            const ulonglong2 A0 = sA2[k * 16 + 2 * ci];
            const ulonglong2 A1 = sA2[k * 16 + 2 * ci + 1];
            unsigned long long ap[4] = {A0.x, A0.y, A1.x, A1.y};
#pragma unroll
            for (int s = 0; s < 8; s++) {
                unsigned long long xd = dup2f(sx[(pi + 32 * s) * XS + k]);
#pragma unroll
                for (int j = 0; j < 4; j++) ffma2(acc2[s][j], xd, ap[j]);
            }
        }
        __syncthreads();

#pragma unroll
        for (int s = 0; s < 8; s++) {
            int p = pi + 32 * s;
            o4[(size_t)t * 4096 + p * 16 + 2 * ci] =
                make_float4(lo32(acc2[s][0]), hi32(acc2[s][0]),
                            lo32(acc2[s][1]), hi32(acc2[s][1]));
            o4[(size_t)t * 4096 + p * 16 + 2 * ci + 1] =
                make_float4(lo32(acc2[s][2]), hi32(acc2[s][2]),
                            lo32(acc2[s][3]), hi32(acc2[s][3]));
        }
    }
}

// ============================================================================
extern "C" void kernel_launch(void* const* d_in, const int* in_sizes, int n_in,
                              void* d_out, int out_size) {
    (void)in_sizes; (void)n_in; (void)out_size;
    const float* x     = (const float*)d_in[0];
    const int*   perm  = (const int*)d_in[1];
    const float* alpha = (const float*)d_in[2];
    float*       out   = (float*)d_out;

    const int ns_smem    = 3 * 64 * MS * (int)sizeof(float);              // 52224 B
    const int apply_smem = (256 * XS + 4096 + 64) * (int)sizeof(float);   // 86272 B
    cudaFuncSetAttribute(ns_kernel, cudaFuncAttributeMaxDynamicSharedMemorySize, ns_smem);
    cudaFuncSetAttribute(apply_kernel, cudaFuncAttributeMaxDynamicSharedMemorySize, apply_smem);

    gram_kernel<<<dim3(GBLK, BATCH), 256>>>(x);
    cov_kernel<<<BATCH, 256>>>();
    ns_kernel<<<BATCH, 512, ns_smem>>>();
    comb_kernel<<<BATCH, 512>>>(perm, alpha);
    apply_kernel<<<dim3(ABLK, BATCH), 256, apply_smem>>>(x, out);
}

// round 8
// speedup vs baseline: 1.1728x; 1.1240x over previous
#include <cuda_runtime.h>
#include <cstdint>

// WCT: out[b] = alpha*x[b] + (1-alpha)*( M_b * (x[b]-mean_b) + mean_{perm[b]} )
// M_b = cov_{perm[b]}^{1/2} * cov_b^{-1/2}, roots via coupled Newton-Schulz.
// Folded: out = A_b * x + bias_b with A_b = alpha*I + (1-alpha)*M_b.
// R7: gram exploits symmetry (36/64 tiles) + double-buffered staging;
//     cov reduction fused into ns; apply gets register-prefetch of next tile.

#define BATCH 16
#define HW 65536
#define NCH 64
#define GBLK 16                 // gram blocks per batch
#define GPIX (HW / GBLK)        // 4096 pixels per gram block
#define ABLK 16                 // apply blocks per batch
#define APIX (HW / ABLK)        // 4096 pixels per apply block
#define NS_ITERS 6
#define MS 68                   // padded row stride (floats) for 64x64 smem matrices
#define XS 68                   // padded row stride (floats) for pixel tiles
#define GT 288                  // gram threads: 8 pixel-groups x 36 upper tiles

// ---- device scratch (static globals; allocation-free) ----
__device__ float g_part[BATCH][GBLK][NCH * NCH];   // per-block gram partials
__device__ float g_psum[BATCH][GBLK][NCH];         // per-block channel-sum partials
__device__ float g_mean[BATCH][NCH];
__device__ float g_half[BATCH][NCH * NCH];         // cov^{1/2}
__device__ float g_invh[BATCH][NCH * NCH];         // cov^{-1/2}
__device__ float g_At  [BATCH][NCH * NCH];         // A^T: g_At[k*64+c] = A[c][k]
__device__ float g_bias[BATCH][NCH];

// ---- packed f32x2 helpers ----
__device__ __forceinline__ void ffma2(unsigned long long& d,
                                      unsigned long long a,
                                      unsigned long long b) {
    asm("fma.rn.f32x2 %0, %1, %2, %0;" : "+l"(d) : "l"(a), "l"(b));
}
__device__ __forceinline__ unsigned long long fadd2(unsigned long long a,
                                                    unsigned long long b) {
    unsigned long long r;
    asm("add.rn.f32x2 %0, %1, %2;" : "=l"(r) : "l"(a), "l"(b));
    return r;
}
__device__ __forceinline__ unsigned long long dup2f(float v) {
    unsigned long long r;
    unsigned u = __float_as_uint(v);
    asm("mov.b64 %0, {%1, %1};" : "=l"(r) : "r"(u));
    return r;
}
__device__ __forceinline__ float lo32(unsigned long long v) {
    return __uint_as_float((unsigned)v);
}
__device__ __forceinline__ float hi32(unsigned long long v) {
    return __uint_as_float((unsigned)(v >> 32));
}

// ============================================================================
// Kernel 1: Gram + channel sums. grid (GBLK, BATCH), 288 threads.
// Symmetry: only 36 upper 8x8 tiles computed (8 pixel-groups x 36 threads),
// mirrored on writeout. Double-buffered 64-pixel tiles with LDG prefetch.
// ============================================================================
__global__ void __launch_bounds__(GT) gram_kernel(const float* __restrict__ x) {
    __shared__ float tile[2][64 * NCH];            // 2 x 16 KB ping-pong
    __shared__ float red[GT];
    __shared__ unsigned long long ssum2[64];

    const int b   = blockIdx.y;
    const int blk = blockIdx.x;
    const int tid = threadIdx.x;
    const int g   = tid / 36;          // pixel-interleave group 0..7
    const int u   = tid - g * 36;      // upper-triangle tile index 0..35

    // (ti, tj) with ti <= tj from triangle index u
    int r = u, ti = 0;
    while (r >= 8 - ti) { r -= 8 - ti; ++ti; }
    const int tj = ti + r;

    unsigned long long acc2[8][4];
#pragma unroll
    for (int i = 0; i < 8; i++)
#pragma unroll
        for (int j = 0; j < 4; j++) acc2[i][j] = 0ull;

    // channel-pair sums: threads 0..63, pair cp = tid&31, pixel half = tid>>5
    unsigned long long sum2 = 0ull;
    const int cp = tid & 31, ph = tid >> 5;

    const float4* x4 = reinterpret_cast<const float4*>(x) +
                       ((size_t)b * HW + (size_t)blk * GPIX) * (NCH / 4);

    // preload tile 0
    float4 pf[4];
#pragma unroll
    for (int rr = 0; rr < 4; ++rr) {
        int f = tid + GT * rr;
        if (f < 1024) pf[rr] = x4[f];
    }
    {
        float4* t4 = reinterpret_cast<float4*>(tile[0]);
#pragma unroll
        for (int rr = 0; rr < 4; ++rr) {
            int f = tid + GT * rr;
            if (f < 1024) t4[f] = pf[rr];
        }
    }
    __syncthreads();

    for (int t = 0; t < GPIX / 64; ++t) {
        const int cb = t & 1;
        // issue prefetch of next tile (latency hidden by compute below)
        if (t + 1 < GPIX / 64) {
#pragma unroll
            for (int rr = 0; rr < 4; ++rr) {
                int f = tid + GT * rr;
                if (f < 1024) pf[rr] = x4[(size_t)(t + 1) * 1024 + f];
            }
        }

        const float4*     t4c = reinterpret_cast<const float4*>(tile[cb]);
        const ulonglong2* tb2 = reinterpret_cast<const ulonglong2*>(tile[cb]);

#pragma unroll 4
        for (int p = g; p < 64; p += 8) {
            const float4 a0 = t4c[p * 16 + 2 * ti];
            const float4 a1 = t4c[p * 16 + 2 * ti + 1];
            const ulonglong2 b0 = tb2[p * 16 + 2 * tj];
            const ulonglong2 b1 = tb2[p * 16 + 2 * tj + 1];
            float av[8] = {a0.x, a0.y, a0.z, a0.w, a1.x, a1.y, a1.z, a1.w};
            unsigned long long bp[4] = {b0.x, b0.y, b1.x, b1.y};
#pragma unroll
            for (int i = 0; i < 8; i++) {
                unsigned long long ad = dup2f(av[i]);
#pragma unroll
                for (int j = 0; j < 4; j++) ffma2(acc2[i][j], ad, bp[j]);
            }
        }

        if (tid < 64) {
            const unsigned long long* tp =
                reinterpret_cast<const unsigned long long*>(tile[cb]);
#pragma unroll 8
            for (int p = ph; p < 64; p += 2)
                sum2 = fadd2(sum2, tp[p * 32 + cp]);
        }
        __syncthreads();                       // everyone done reading tile[cb^1]? done reading cb

        if (t + 1 < GPIX / 64) {
            float4* t4n = reinterpret_cast<float4*>(tile[cb ^ 1]);
#pragma unroll
            for (int rr = 0; rr < 4; ++rr) {
                int f = tid + GT * rr;
                if (f < 1024) t4n[f] = pf[rr];
            }
            __syncthreads();
        }
    }

    // channel sums: combine the two pixel-halves
    if (tid < 64) ssum2[tid] = sum2;
    __syncthreads();
    if (tid < 32) {
        unsigned long long v = fadd2(ssum2[tid], ssum2[tid + 32]);
        g_psum[b][blk][2 * tid]     = lo32(v);
        g_psum[b][blk][2 * tid + 1] = hi32(v);
    }
    __syncthreads();

    // reduce acc over 8 pixel-groups; write tile and its mirror
#pragma unroll 1
    for (int e = 0; e < 64; ++e) {
        const int ii = e >> 3, jj = e & 7;
        const unsigned long long v2 = acc2[ii][jj >> 1];
        red[g * 36 + u] = (jj & 1) ? hi32(v2) : lo32(v2);
        __syncthreads();
        if (tid < 36) {
            float v = 0.f;
#pragma unroll
            for (int gg = 0; gg < 8; ++gg) v += red[gg * 36 + tid];
            const int row = 8 * ti + ii;
            const int col = 8 * tj + jj;
            g_part[b][blk][row * NCH + col] = v;
            g_part[b][blk][col * NCH + row] = v;   // symmetry (diag: same value)
        }
        __syncthreads();
    }
}

// ============================================================================
// 64x64 smem matmul helpers (stride MS), packed f32x2.
// ============================================================================
__device__ __forceinline__ void mm64p(const float* __restrict__ A,
                                      const float* __restrict__ B,
                                      unsigned long long r2[8], int i, int j0) {
#pragma unroll
    for (int q = 0; q < 8; q++) r2[q] = 0ull;
#pragma unroll 8
    for (int k = 0; k < 64; ++k) {
        unsigned long long ad = dup2f(A[i * MS + k]);
        const ulonglong2* b2 = reinterpret_cast<const ulonglong2*>(B + k * MS + j0);
        ulonglong2 x0 = b2[0], x1 = b2[1], x2 = b2[2], x3 = b2[3];
        ffma2(r2[0], ad, x0.x); ffma2(r2[1], ad, x0.y);
        ffma2(r2[2], ad, x1.x); ffma2(r2[3], ad, x1.y);
        ffma2(r2[4], ad, x2.x); ffma2(r2[5], ad, x2.y);
        ffma2(r2[6], ad, x3.x); ffma2(r2[7], ad, x3.y);
    }
}

__device__ __forceinline__ void mm64p8(const float* __restrict__ A,
                                       const float* __restrict__ B,
                                       unsigned long long r2[4], int i, int j0) {
#pragma unroll
    for (int q = 0; q < 4; q++) r2[q] = 0ull;
#pragma unroll 8
    for (int k = 0; k < 64; ++k) {
        unsigned long long ad = dup2f(A[i * MS + k]);
        const ulonglong2* b2 = reinterpret_cast<const ulonglong2*>(B + k * MS + j0);
        ulonglong2 x0 = b2[0], x1 = b2[1];
        ffma2(r2[0], ad, x0.x); ffma2(r2[1], ad, x0.y);
        ffma2(r2[2], ad, x1.x); ffma2(r2[3], ad, x1.y);
    }
}

// ============================================================================
// Kernel 2: fused cov-reduction + Newton-Schulz. grid BATCH, 512 threads.
// Y->cov^{1/2}, Z->cov^{-1/2}. Dynamic smem: 3 * 64 * MS floats (52 KB).
// ============================================================================
__global__ void __launch_bounds__(512) ns_kernel() {
    extern __shared__ float dsm[];
    float* sY = dsm;
    float* sZ = sY + 64 * MS;
    float* sT = sZ + 64 * MS;
    __shared__ float mean_s[NCH];

    const int b = blockIdx.x, tid = threadIdx.x;
    const int i8  = tid >> 3, j8 = (tid & 7) * 8;            // T-phase mapping
    const int u   = tid & 255;
    const int i16 = u >> 2, j16 = (u & 3) * 16;              // half-phase mapping

    // ---- fused cov: means ----
    if (tid < NCH) {
        float s = 0.f;
#pragma unroll
        for (int k = 0; k < GBLK; ++k) s += g_psum[b][k][tid];
        float m = s * (1.f / (float)HW);
        mean_s[tid] = m;
        g_mean[b][tid] = m;
    }
    __syncthreads();

    // ---- fused cov: reduce partials into sZ (temp) ----
    const float inv_d = 1.f / (float)(HW - 1);
    for (int e = tid; e < 4096; e += 512) {
        float s = 0.f;
#pragma unroll
        for (int k = 0; k < GBLK; ++k) s += g_part[b][k][e];
        int i = e >> 6, j = e & 63;
        sZ[i * MS + j] = (s - (float)HW * mean_s[i] * mean_s[j]) * inv_d;
    }
    __syncthreads();

    // infinity-norm of cov (>= largest eigenvalue for SPD)
    if (tid < 64) {
        float s = 0.f;
        for (int j = 0; j < 64; ++j) s += fabsf(sZ[tid * MS + j]);
        sY[tid] = s;
    }
    __syncthreads();
    if (tid == 0) {
        float m = 0.f;
        for (int r = 0; r < 64; ++r) m = fmaxf(m, sY[r]);
        sT[0] = m;
    }
    __syncthreads();
    const float c = sT[0];
    const float inv_c = 1.f / c;
    __syncthreads();

    for (int e = tid; e < 4096; e += 512) {
        int r = e >> 6, q = e & 63;
        float v = sZ[r * MS + q];
        sY[r * MS + q] = v * inv_c;
        sZ[r * MS + q] = (r == q) ? 1.f : 0.f;
    }
    __syncthreads();

    for (int it = 0; it < NS_ITERS; ++it) {
        // T = 1.5 I - 0.5 * Z*Y   (all 512 threads, 8-wide)
        unsigned long long t2[4];
        mm64p8(sZ, sY, t2, i8, j8);
#pragma unroll
        for (int q = 0; q < 4; q++) {
            int j = j8 + 2 * q;
            sT[i8 * MS + j]     = ((i8 == j)     ? 1.5f : 0.f) - 0.5f * lo32(t2[q]);
            sT[i8 * MS + j + 1] = ((i8 == j + 1) ? 1.5f : 0.f) - 0.5f * hi32(t2[q]);
        }
        __syncthreads();

        // Y' = Y*T (threads 0..255), Z' = T*Z (threads 256..511), concurrent
        unsigned long long r2[8];
        if (tid < 256) mm64p(sY, sT, r2, i16, j16);
        else           mm64p(sT, sZ, r2, i16, j16);
        __syncthreads();
        float* dst = (tid < 256) ? sY : sZ;
#pragma unroll
        for (int q = 0; q < 8; q++) {
            dst[i16 * MS + j16 + 2 * q]     = lo32(r2[q]);
            dst[i16 * MS + j16 + 2 * q + 1] = hi32(r2[q]);
        }
        __syncthreads();
    }

    const float sc = sqrtf(c), isc = rsqrtf(c);
    for (int e = tid; e < 4096; e += 512) {
        int r = e >> 6, q = e & 63;
        g_half[b][e] = sY[r * MS + q] * sc;
        g_invh[b][e] = sZ[r * MS + q] * isc;
    }
}

// ============================================================================
// Kernel 3: A_b = alpha I + (1-alpha) * half[perm[b]] * invh[b] (stored A^T),
//           bias_b = (1-alpha)*(mean[perm[b]] - M*mean[b]). grid BATCH, 512.
// ============================================================================
__global__ void __launch_bounds__(512) comb_kernel(const int* __restrict__ perm,
                                                   const float* __restrict__ alpha) {
    __shared__ float sS[64 * MS], sTi[64 * MS], red[512];
    const int b = blockIdx.x, tid = threadIdx.x;
    const int pb = perm[b];
    const float al = alpha[b];
    const float oma = 1.f - al;

    for (int e = tid; e < 4096; e += 512) {
        int r = e >> 6, q = e & 63;
        sS [r * MS + q] = g_half[pb][e];
        sTi[r * MS + q] = g_invh[b][e];
    }
    __syncthreads();

    const int i = tid >> 3, j0 = (tid & 7) * 8;
    unsigned long long m2[4];
    mm64p8(sS, sTi, m2, i, j0);   // M[i][j0..j0+7]

    float m[8];
#pragma unroll
    for (int q = 0; q < 4; q++) { m[2 * q] = lo32(m2[q]); m[2 * q + 1] = hi32(m2[q]); }

    float pdot = 0.f;
#pragma unroll
    for (int q = 0; q < 8; q++) {
        int j = j0 + q;
        g_At[b][j * 64 + i] = ((i == j) ? al : 0.f) + oma * m[q];  // A^T[j][i]=A[i][j]
        pdot += m[q] * g_mean[b][j];
    }
    red[tid] = pdot;
    __syncthreads();
    if (tid < 64) {
        float dot = 0.f;
#pragma unroll
        for (int t = 0; t < 8; t++) dot += red[tid * 8 + t];
        g_bias[b][tid] = oma * (g_mean[pb][tid] - dot);
    }
}

// ============================================================================
// Kernel 4: out[p] = A*x[p] + bias. grid (ABLK, BATCH), 256 threads.
// 256-pixel tiles, 8px x 8ch (4 packed pairs) per thread.
// Register prefetch of the NEXT tile overlaps DRAM fetch with compute.
// Dynamic smem: 256*XS + 4096 + 64 floats (~86 KB).
// ============================================================================
__global__ void __launch_bounds__(256) apply_kernel(const float* __restrict__ x,
                                                    float* __restrict__ out) {
    extern __shared__ float dsm[];
    float* sx = dsm;                 // 256 * XS
    float* sA = sx + 256 * XS;       // 64*64 (A^T, row k contiguous in c)
    float* sb = sA + 4096;           // 64

    const int b = blockIdx.y, blk = blockIdx.x, tid = threadIdx.x;

    for (int e = tid; e < 4096; e += 256) sA[e] = g_At[b][e];
    if (tid < 64) sb[tid] = g_bias[b][tid];

    const int ci = tid & 7;          // channel group: c0 = 8*ci
    const int pi = tid >> 3;         // pixel slot 0..31 ; pixels pi + 32*s
    const int c0 = ci * 8;

    const float4* x4 = reinterpret_cast<const float4*>(x) +
                       ((size_t)b * HW + (size_t)blk * APIX) * (NCH / 4);
    float4* o4 = reinterpret_cast<float4*>(out) +
                 ((size_t)b * HW + (size_t)blk * APIX) * (NCH / 4);
    float4* sx4 = reinterpret_cast<float4*>(sx);
    const ulonglong2* sA2 = reinterpret_cast<const ulonglong2*>(sA);
    const unsigned long long* sb2 =
        reinterpret_cast<const unsigned long long*>(sb + c0);

    // preload tile 0 into registers
    float4 pf[16];
#pragma unroll
    for (int k2 = 0; k2 < 16; ++k2) pf[k2] = x4[tid + 256 * k2];

    for (int t = 0; t < APIX / 256; ++t) {
        __syncthreads();             // sx free (prev compute done) / sA visible
#pragma unroll
        for (int k2 = 0; k2 < 16; ++k2) {
            int f = tid + 256 * k2;
            int p = f >> 4, q = f & 15;
            sx4[p * (XS / 4) + q] = pf[k2];
        }
        __syncthreads();

        if (t + 1 < APIX / 256) {    // issue next-tile loads; latency under compute
#pragma unroll
            for (int k2 = 0; k2 < 16; ++k2)
                pf[k2] = x4[(size_t)(t + 1) * 4096 + tid + 256 * k2];
        }

        unsigned long long acc2[8][4];
#pragma unroll
        for (int s = 0; s < 8; s++)
#pragma unroll
            for (int j = 0; j < 4; j++) acc2[s][j] = sb2[j];

#pragma unroll 8
        for (int k = 0; k < 64; ++k) {
            const ulonglong2 A0 = sA2[k * 16 + 2 * ci];
            const ulonglong2 A1 = sA2[k * 16 + 2 * ci + 1];
            unsigned long long ap[4] = {A0.x, A0.y, A1.x, A1.y};
#pragma unroll
            for (int s = 0; s < 8; s++) {
                unsigned long long xd = dup2f(sx[(pi + 32 * s) * XS + k]);
#pragma unroll
                for (int j = 0; j < 4; j++) ffma2(acc2[s][j], xd, ap[j]);
            }
        }

#pragma unroll
        for (int s = 0; s < 8; s++) {
            int p = pi + 32 * s;
            o4[(size_t)t * 4096 + p * 16 + 2 * ci] =
                make_float4(lo32(acc2[s][0]), hi32(acc2[s][0]),
                            lo32(acc2[s][1]), hi32(acc2[s][1]));
            o4[(size_t)t * 4096 + p * 16 + 2 * ci + 1] =
                make_float4(lo32(acc2[s][2]), hi32(acc2[s][2]),
                            lo32(acc2[s][3]), hi32(acc2[s][3]));
        }
    }
}

// ============================================================================
extern "C" void kernel_launch(void* const* d_in, const int* in_sizes, int n_in,
                              void* d_out, int out_size) {
    (void)in_sizes; (void)n_in; (void)out_size;
    const float* x     = (const float*)d_in[0];
    const int*   perm  = (const int*)d_in[1];
    const float* alpha = (const float*)d_in[2];
    float*       out   = (float*)d_out;

    const int ns_smem    = 3 * 64 * MS * (int)sizeof(float);              // 52224 B
    const int apply_smem = (256 * XS + 4096 + 64) * (int)sizeof(float);   // 86272 B
    cudaFuncSetAttribute(ns_kernel, cudaFuncAttributeMaxDynamicSharedMemorySize, ns_smem);
    cudaFuncSetAttribute(apply_kernel, cudaFuncAttributeMaxDynamicSharedMemorySize, apply_smem);

    gram_kernel<<<dim3(GBLK, BATCH), GT>>>(x);
    ns_kernel<<<BATCH, 512, ns_smem>>>();
    comb_kernel<<<BATCH, 512>>>(perm, alpha);
    apply_kernel<<<dim3(ABLK, BATCH), 256, apply_smem>>>(x, out);
}